// round 5
// baseline (speedup 1.0000x reference)
#include <cuda_runtime.h>
#include <math.h>

#define BB   64
#define CIN  2304
#define DD   512
#define HW   196
#define K9   9

// ---------------- scratch (device globals; no allocation allowed) ----------
__device__ float g_x1  [BB * DD * HW];   // reduced input (residual branch)
__device__ float g_q   [BB * DD * HW];
__device__ float g_k   [BB * DD * HW];
__device__ float g_v   [BB * DD * HW];
__device__ float g_virt[BB * DD * HW];   // attention output -> GN in-place
__device__ float g_vc  [BB * DD * HW];   // final conv output
__device__ float g_wt  [4 * DD * DD * K9]; // conv weights transposed [cin][dout][k]

// ---------------- weight transpose: [dout][cin][9] -> [cin][dout][9] -------
__global__ void transpose_w(const float* __restrict__ wq,
                            const float* __restrict__ wk,
                            const float* __restrict__ wv,
                            const float* __restrict__ wc) {
    int idx = blockIdx.x * blockDim.x + threadIdx.x;
    if (idx >= DD * DD * K9) return;
    int k    = idx % K9;
    int dout = (idx / K9) % DD;
    int cin  = idx / (K9 * DD);
    int src  = (dout * DD + cin) * K9 + k;
    g_wt[0 * DD * DD * K9 + idx] = wq[src];
    g_wt[1 * DD * DD * K9 + idx] = wk[src];
    g_wt[2 * DD * DD * K9 + idx] = wv[src];
    g_wt[3 * DD * DD * K9 + idx] = wc[src];
}

// ---------------- 1x1 reduce conv: per-batch GEMM [512 x 2304] x [2304 x 196]
// block: (b, 64-dout group). 224 threads = 28 pixel-groups x 8 dout-groups.
// thread tile: 8 douts x 7 pixels.
__global__ __launch_bounds__(224) void conv_reduce(const float* __restrict__ x,
                                                   const float* __restrict__ wr) {
    __shared__ float xs[8][HW];
    __shared__ float ws[8][64];
    int b   = blockIdx.x;
    int d0  = blockIdx.y * 64;
    int tid = threadIdx.x;
    int pg  = tid / 8;   // 0..27
    int dg  = tid % 8;   // 0..7
    int pb  = pg * 7;

    float acc[8][7];
#pragma unroll
    for (int d = 0; d < 8; d++)
#pragma unroll
        for (int p = 0; p < 7; p++) acc[d][p] = 0.f;

    const float* xb = x + (size_t)b * CIN * HW;

    for (int c0 = 0; c0 < CIN; c0 += 8) {
        for (int i = tid; i < 8 * HW; i += 224) {
            int cc = i / HW, pp = i % HW;
            xs[cc][pp] = xb[(c0 + cc) * HW + pp];
        }
        for (int i = tid; i < 512; i += 224) {
            int dd = i >> 3, cc = i & 7;
            ws[cc][dd] = wr[(size_t)(d0 + dd) * CIN + c0 + cc];
        }
        __syncthreads();
#pragma unroll
        for (int cc = 0; cc < 8; cc++) {
            float wv[8], xv[7];
#pragma unroll
            for (int d = 0; d < 8; d++) wv[d] = ws[cc][dg * 8 + d];
#pragma unroll
            for (int p = 0; p < 7; p++) xv[p] = xs[cc][pb + p];
#pragma unroll
            for (int d = 0; d < 8; d++)
#pragma unroll
                for (int p = 0; p < 7; p++) acc[d][p] += wv[d] * xv[p];
        }
        __syncthreads();
    }
    float* outb = g_x1 + (size_t)b * DD * HW;
#pragma unroll
    for (int d = 0; d < 8; d++)
#pragma unroll
        for (int p = 0; p < 7; p++)
            outb[(d0 + dg * 8 + d) * HW + pb + p] = acc[d][p];
}

// ---------------- 3x3 SAME conv, D=512 -> D=512, 14x14 ---------------------
// block: (b, 64-dout group, which-conv). 224 threads, tile 8 douts x 7 pixels.
// weights pre-transposed to [cin][dout][9]. 4 cin per iter.
// blockIdx.z selects {q, k, v} weight set + output (merged launch).
__global__ __launch_bounds__(224) void conv3x3_qkv(const float* __restrict__ in) {
    __shared__ float xs[4][256];       // padded 16x16 tile per cin
    __shared__ float ws[4][64 * K9];   // 64 douts x 9

    int b   = blockIdx.x;
    int d0  = blockIdx.y * 64;
    int z   = blockIdx.z;              // 0=q, 1=k, 2=v
    int tid = threadIdx.x;
    int pg  = tid / 8;   // 0..27
    int dg  = tid % 8;   // 0..7

    const float* wt = g_wt + (size_t)z * DD * DD * K9;
    float* out = (z == 0) ? g_q : (z == 1) ? g_k : g_v;

    int pbase[7];
#pragma unroll
    for (int p = 0; p < 7; p++) {
        int pix = pg * 7 + p;
        pbase[p] = (pix / 14) * 16 + (pix % 14);
    }

    float acc[8][7];
#pragma unroll
    for (int d = 0; d < 8; d++)
#pragma unroll
        for (int p = 0; p < 7; p++) acc[d][p] = 0.f;

    const float* inb = in + (size_t)b * DD * HW;

    for (int c = 0; c < DD; c += 4) {
        for (int i = tid; i < 4 * 256; i += 224) {
            int cc = i >> 8, j = i & 255;
            int r = (j >> 4) - 1, col = (j & 15) - 1;
            float v = 0.f;
            if (r >= 0 && r < 14 && col >= 0 && col < 14)
                v = inb[(c + cc) * HW + r * 14 + col];
            xs[cc][j] = v;
        }
        for (int i = tid; i < 4 * 576; i += 224) {
            int cc = i / 576, j = i % 576;
            ws[cc][j] = wt[(size_t)(c + cc) * DD * K9 + d0 * K9 + j];
        }
        __syncthreads();
#pragma unroll
        for (int cc = 0; cc < 4; cc++) {
#pragma unroll
            for (int kh = 0; kh < 3; kh++) {
#pragma unroll
                for (int kw = 0; kw < 3; kw++) {
                    int off = kh * 16 + kw;
                    int kk  = kh * 3 + kw;
                    float wv[8], xv[7];
#pragma unroll
                    for (int d = 0; d < 8; d++) wv[d] = ws[cc][(dg * 8 + d) * K9 + kk];
#pragma unroll
                    for (int p = 0; p < 7; p++) xv[p] = xs[cc][pbase[p] + off];
#pragma unroll
                    for (int d = 0; d < 8; d++)
#pragma unroll
                        for (int p = 0; p < 7; p++) acc[d][p] += wv[d] * xv[p];
                }
            }
        }
        __syncthreads();
    }
    float* outb = out + (size_t)b * DD * HW;
#pragma unroll
    for (int d = 0; d < 8; d++)
#pragma unroll
        for (int p = 0; p < 7; p++)
            outb[(d0 + dg * 8 + d) * HW + pg * 7 + p] = acc[d][p];
}

// ---------------- 3x3 SAME conv (single, for the final conv) ---------------
__global__ __launch_bounds__(224) void conv3x3_k(const float* __restrict__ in,
                                                 const float* __restrict__ wt,
                                                 float* __restrict__ out) {
    __shared__ float xs[4][256];
    __shared__ float ws[4][64 * K9];

    int b   = blockIdx.x;
    int d0  = blockIdx.y * 64;
    int tid = threadIdx.x;
    int pg  = tid / 8;
    int dg  = tid % 8;

    int pbase[7];
#pragma unroll
    for (int p = 0; p < 7; p++) {
        int pix = pg * 7 + p;
        pbase[p] = (pix / 14) * 16 + (pix % 14);
    }

    float acc[8][7];
#pragma unroll
    for (int d = 0; d < 8; d++)
#pragma unroll
        for (int p = 0; p < 7; p++) acc[d][p] = 0.f;

    const float* inb = in + (size_t)b * DD * HW;

    for (int c = 0; c < DD; c += 4) {
        for (int i = tid; i < 4 * 256; i += 224) {
            int cc = i >> 8, j = i & 255;
            int r = (j >> 4) - 1, col = (j & 15) - 1;
            float v = 0.f;
            if (r >= 0 && r < 14 && col >= 0 && col < 14)
                v = inb[(c + cc) * HW + r * 14 + col];
            xs[cc][j] = v;
        }
        for (int i = tid; i < 4 * 576; i += 224) {
            int cc = i / 576, j = i % 576;
            ws[cc][j] = wt[(size_t)(c + cc) * DD * K9 + d0 * K9 + j];
        }
        __syncthreads();
#pragma unroll
        for (int cc = 0; cc < 4; cc++) {
#pragma unroll
            for (int kh = 0; kh < 3; kh++) {
#pragma unroll
                for (int kw = 0; kw < 3; kw++) {
                    int off = kh * 16 + kw;
                    int kk  = kh * 3 + kw;
                    float wv[8], xv[7];
#pragma unroll
                    for (int d = 0; d < 8; d++) wv[d] = ws[cc][(dg * 8 + d) * K9 + kk];
#pragma unroll
                    for (int p = 0; p < 7; p++) xv[p] = xs[cc][pbase[p] + off];
#pragma unroll
                    for (int d = 0; d < 8; d++)
#pragma unroll
                        for (int p = 0; p < 7; p++) acc[d][p] += wv[d] * xv[p];
                }
            }
        }
        __syncthreads();
    }
    float* outb = out + (size_t)b * DD * HW;
#pragma unroll
    for (int d = 0; d < 8; d++)
#pragma unroll
        for (int p = 0; p < 7; p++)
            outb[(d0 + dg * 8 + d) * HW + pg * 7 + p] = acc[d][p];
}

// ---------------- fused attention per pixel --------------------------------
__global__ __launch_bounds__(256) void attention_k() {
    __shared__ float att[64][65];
    __shared__ float buf[4224];

    int p   = blockIdx.x;
    int tid = threadIdx.x;
    int ti  = tid >> 4, tj = tid & 15;
    int i0  = ti * 4,  j0 = tj * 4;

    float acc[4][4];
#pragma unroll
    for (int a = 0; a < 4; a++)
#pragma unroll
        for (int bb = 0; bb < 4; bb++) acc[a][bb] = 0.f;

    for (int c0 = 0; c0 < DD; c0 += 32) {
        for (int idx = tid; idx < 2048; idx += 256) {
            int i = idx >> 5, cc = idx & 31;
            buf[i * 33 + cc]        = g_q[(size_t)(i * DD + c0 + cc) * HW + p];
            buf[2112 + i * 33 + cc] = g_k[(size_t)(i * DD + c0 + cc) * HW + p];
        }
        __syncthreads();
#pragma unroll 4
        for (int cc = 0; cc < 32; cc++) {
            float qv[4], kv[4];
#pragma unroll
            for (int a = 0; a < 4; a++) qv[a] = buf[(i0 + a) * 33 + cc];
#pragma unroll
            for (int bb = 0; bb < 4; bb++) kv[bb] = buf[2112 + (j0 + bb) * 33 + cc];
#pragma unroll
            for (int a = 0; a < 4; a++)
#pragma unroll
                for (int bb = 0; bb < 4; bb++) acc[a][bb] += qv[a] * kv[bb];
        }
        __syncthreads();
    }
    const float rnorm = 0.0441941738241592f;  // 1/sqrt(512)
#pragma unroll
    for (int a = 0; a < 4; a++)
#pragma unroll
        for (int bb = 0; bb < 4; bb++) att[i0 + a][j0 + bb] = acc[a][bb] * rnorm;
    __syncthreads();

    if (tid < 64) {
        float m = -1e30f;
        for (int j = 0; j < 64; j++) m = fmaxf(m, att[tid][j]);
        float s = 0.f;
        for (int j = 0; j < 64; j++) { float e = expf(att[tid][j] - m); att[tid][j] = e; s += e; }
        float inv = 1.f / s;
        for (int j = 0; j < 64; j++) att[tid][j] *= inv;
    }
    __syncthreads();

    for (int c0 = 0; c0 < DD; c0 += 64) {
        for (int idx = tid; idx < 4096; idx += 256) {
            int j = idx >> 6, cc = idx & 63;
            buf[j * 65 + cc] = g_v[(size_t)(j * DD + c0 + cc) * HW + p];
        }
        __syncthreads();
        float a2[4][4];
#pragma unroll
        for (int a = 0; a < 4; a++)
#pragma unroll
            for (int bb = 0; bb < 4; bb++) a2[a][bb] = 0.f;
#pragma unroll 4
        for (int j = 0; j < 64; j++) {
            float av[4], vv[4];
#pragma unroll
            for (int a = 0; a < 4; a++) av[a] = att[i0 + a][j];
#pragma unroll
            for (int bb = 0; bb < 4; bb++) vv[bb] = buf[j * 65 + j0 + bb];
#pragma unroll
            for (int a = 0; a < 4; a++)
#pragma unroll
                for (int bb = 0; bb < 4; bb++) a2[a][bb] += av[a] * vv[bb];
        }
#pragma unroll
        for (int a = 0; a < 4; a++)
#pragma unroll
            for (int bb = 0; bb < 4; bb++)
                g_virt[(size_t)((i0 + a) * DD + c0 + j0 + bb) * HW + p] = a2[a][bb];
        __syncthreads();
    }
}

// ---------------- GroupNorm(1 group) + affine + ReLU, in place -------------
__global__ __launch_bounds__(256) void groupnorm_k(const float* __restrict__ gamma,
                                                   const float* __restrict__ beta) {
    int b = blockIdx.x, tid = threadIdx.x;
    float* v = g_virt + (size_t)b * DD * HW;
    float s1 = 0.f, s2 = 0.f;
    for (int i = tid; i < DD * HW; i += 256) { float x = v[i]; s1 += x; s2 += x * x; }
    __shared__ float sh1[256], sh2[256];
    sh1[tid] = s1; sh2[tid] = s2; __syncthreads();
    for (int s = 128; s > 0; s >>= 1) {
        if (tid < s) { sh1[tid] += sh1[tid + s]; sh2[tid] += sh2[tid + s]; }
        __syncthreads();
    }
    const float invn = 1.f / (DD * HW);
    float mean = sh1[0] * invn;
    float var  = sh2[0] * invn - mean * mean;
    float rstd = rsqrtf(var + 1e-5f);
    for (int i = tid; i < DD * HW; i += 256) {
        int c = i / HW;
        float x = (v[i] - mean) * rstd * gamma[c] + beta[c];
        v[i] = fmaxf(x, 0.f);
    }
}

// ---------------- residual + global avg pool + linear head -----------------
__global__ __launch_bounds__(256) void final_k(const float* __restrict__ wp,
                                               float* __restrict__ out) {
    int b = blockIdx.x, tid = threadIdx.x;
    const float* x1 = g_x1 + (size_t)b * DD * HW;
    const float* vc = g_vc + (size_t)b * DD * HW;
    float acc = 0.f;
    for (int d = tid; d < DD; d += 256) {
        float s = 0.f;
        for (int p = 0; p < HW; p++) s += x1[d * HW + p] + vc[d * HW + p];
        acc += s * wp[d];
    }
    __shared__ float sh[256];
    sh[tid] = acc; __syncthreads();
    for (int s = 128; s > 0; s >>= 1) {
        if (tid < s) sh[tid] += sh[tid + s];
        __syncthreads();
    }
    if (tid == 0) out[b] = sh[0] * (1.f / HW);
}

// ---------------------------------------------------------------------------
extern "C" void kernel_launch(void* const* d_in, const int* in_sizes, int n_in,
                              void* d_out, int out_size) {
    const float* x        = (const float*)d_in[0];
    const float* w_reduce = (const float*)d_in[1];
    const float* w_q      = (const float*)d_in[2];
    const float* w_k      = (const float*)d_in[3];
    const float* w_v      = (const float*)d_in[4];
    const float* w_conv   = (const float*)d_in[5];
    const float* gamma    = (const float*)d_in[6];
    const float* beta     = (const float*)d_in[7];
    const float* w_pred   = (const float*)d_in[8];
    float* out = (float*)d_out;

    float *p_x1, *p_virt, *p_vc, *p_wt;
    cudaGetSymbolAddress((void**)&p_x1,   g_x1);
    cudaGetSymbolAddress((void**)&p_virt, g_virt);
    cudaGetSymbolAddress((void**)&p_vc,   g_vc);
    cudaGetSymbolAddress((void**)&p_wt,   g_wt);

    int nw = DD * DD * K9;
    transpose_w<<<(nw + 255) / 256, 256>>>(w_q, w_k, w_v, w_conv);

    conv_reduce<<<dim3(BB, 8), 224>>>(x, w_reduce);

    conv3x3_qkv<<<dim3(BB, 8, 3), 224>>>(p_x1);

    attention_k<<<HW, 256>>>();
    groupnorm_k<<<BB, 256>>>(gamma, beta);

    conv3x3_k<<<dim3(BB, 8), 224>>>(p_virt, p_wt + 3 * (size_t)nw, p_vc);

    final_k<<<BB, 256>>>(w_pred, out);
}

// round 15
// speedup vs baseline: 3.7274x; 3.7274x over previous
#include <cuda_runtime.h>
#include <stdint.h>

#define BB   64
#define CIN  2304
#define DD   512
#define HW   196
#define PS   224          // padded pixel stride (28*8)
#define K9   9
#define KQ   (DD * K9)    // 4608
#define KC   32           // GEMM k-chunk

// ---------------- scratch (device globals; no allocation allowed) ----------
__device__ float g_xpad[BB * CIN * PS];   // padded+tf32-rounded input x
__device__ float g_col [BB * KQ * PS];    // im2col buffer (tf32-rounded)
__device__ float g_x1  [BB * DD * PS];    // reduced input (residual branch)
__device__ float g_q   [BB * DD * PS];
__device__ float g_k   [BB * DD * PS];
__device__ float g_v   [BB * DD * PS];
__device__ float g_virt[BB * DD * PS];    // attention out -> GN in place
__device__ float g_vc  [BB * DD * PS];    // final conv out
__device__ float g_wtT [4 * KQ * DD];     // conv weights transposed [k][dout], tf32-rounded
__device__ float g_wrT [CIN * DD];        // reduce weights transposed [k][dout]

// ---------------- helpers --------------------------------------------------
__device__ __forceinline__ float rnd_tf32(float x) {
    uint32_t u;
    asm("cvt.rna.tf32.f32 %0, %1;" : "=r"(u) : "f"(x));
    return __uint_as_float(u);
}
__device__ __forceinline__ void cp16(uint32_t s, const void* g) {
    asm volatile("cp.async.cg.shared.global [%0], [%1], 16;\n" :: "r"(s), "l"(g));
}
__device__ __forceinline__ void cp8(uint32_t s, const void* g) {
    asm volatile("cp.async.ca.shared.global [%0], [%1], 8;\n" :: "r"(s), "l"(g));
}
__device__ __forceinline__ void cp_commit() {
    asm volatile("cp.async.commit_group;\n");
}
template <int N>
__device__ __forceinline__ void cp_wait() {
    asm volatile("cp.async.wait_group %0;\n" :: "n"(N));
}
__device__ __forceinline__ void mma8(float* c, const uint32_t* a, uint32_t b0, uint32_t b1) {
    asm volatile(
        "mma.sync.aligned.m16n8k8.row.col.f32.tf32.tf32.f32 "
        "{%0,%1,%2,%3}, {%4,%5,%6,%7}, {%8,%9}, {%0,%1,%2,%3};\n"
        : "+f"(c[0]), "+f"(c[1]), "+f"(c[2]), "+f"(c[3])
        : "r"(a[0]), "r"(a[1]), "r"(a[2]), "r"(a[3]), "r"(b0), "r"(b1));
}

// ---------------- weight prep: transpose + tf32 round ----------------------
__global__ void prep_w(const float* __restrict__ wq, const float* __restrict__ wk,
                       const float* __restrict__ wv, const float* __restrict__ wc,
                       const float* __restrict__ wr) {
    int idx = blockIdx.x * 256 + threadIdx.x;
    if (idx >= KQ * DD) return;
    int k = idx / DD, d = idx % DD;
    g_wtT[0 * KQ * DD + idx] = rnd_tf32(wq[(size_t)d * KQ + k]);
    g_wtT[1 * KQ * DD + idx] = rnd_tf32(wk[(size_t)d * KQ + k]);
    g_wtT[2 * KQ * DD + idx] = rnd_tf32(wv[(size_t)d * KQ + k]);
    g_wtT[3 * KQ * DD + idx] = rnd_tf32(wc[(size_t)d * KQ + k]);
    if (k < CIN) g_wrT[idx] = rnd_tf32(wr[(size_t)d * CIN + k]);
}

// ---------------- pad + round x: [b][2304][196] -> [b][2304][224] ----------
__global__ void pad_x(const float* __restrict__ x) {
#pragma unroll
    for (int j = 0; j < 4; j++) {
        int i = blockIdx.x * 1024 + j * 256 + threadIdx.x;
        int p = i % PS;
        int bc = i / PS;
        float v = 0.f;
        if (p < HW) v = rnd_tf32(x[(size_t)bc * HW + p]);
        g_xpad[i] = v;
    }
}

// ---------------- im2col: src [b][512][PS] -> g_col [b][4608][PS] ----------
__global__ void im2col_k(const float* __restrict__ src) {
#pragma unroll
    for (int j = 0; j < 4; j++) {
        int i = blockIdx.x * 1024 + j * 256 + threadIdx.x;
        int p = i % PS;
        int kr = (i / PS) % KQ;
        int b = i / (PS * KQ);
        int cin = kr / 9, kk = kr % 9;
        float v = 0.f;
        if (p < HW) {
            int r = p / 14 + kk / 3 - 1;
            int c = p % 14 + kk % 3 - 1;
            if (r >= 0 && r < 14 && c >= 0 && c < 14)
                v = rnd_tf32(src[((size_t)b * DD + cin) * PS + r * 14 + c]);
        }
        g_col[i] = v;
    }
}

// ---------------- TF32 GEMM core (device body shared by both launchers) ----
__device__ __forceinline__ void gemm_body(const float* __restrict__ A,
                                          const float* __restrict__ B,
                                          float* __restrict__ C, int K,
                                          int b, int d0, int n0) {
    extern __shared__ float sm[];   // 2 stages x (As[32][136] + Bs[32][120])
    int tid = threadIdx.x, lane = tid & 31, wid = tid >> 5;
    int g = lane >> 2, t = lane & 3;
    int m0 = (wid & 3) * 32, n0w = (wid >> 2) * 56;

    const float* Bb = B + (size_t)b * K * PS + n0;

    float acc[2][7][4];
#pragma unroll
    for (int mf = 0; mf < 2; mf++)
#pragma unroll
        for (int nf = 0; nf < 7; nf++)
#pragma unroll
            for (int r = 0; r < 4; r++) acc[mf][nf][r] = 0.f;

    int nk = K / KC;

    auto load_stage = [&](int st, int k0) {
        float* As = sm + st * 8192;
        float* Bs = As + 4352;
        const float* Ag = A + (size_t)k0 * DD + d0;
#pragma unroll
        for (int j = 0; j < 4; j++) {
            int lin = tid + j * 256;          // 0..1023
            int kr = lin >> 5, mg = (lin & 31) << 2;
            cp16((uint32_t)__cvta_generic_to_shared(As + kr * 136 + mg),
                 Ag + (size_t)kr * DD + mg);
        }
        const float* Bg = Bb + (size_t)k0 * PS;
#pragma unroll
        for (int j = 0; j < 7; j++) {
            int lin = tid + j * 256;          // 0..1791
            int kr = lin / 56, c2 = (lin % 56) * 2;
            cp8((uint32_t)__cvta_generic_to_shared(Bs + kr * 120 + c2),
                Bg + (size_t)kr * PS + c2);
        }
    };

    load_stage(0, 0);
    cp_commit();

    for (int kt = 0; kt < nk; kt++) {
        if (kt + 1 < nk) {
            load_stage((kt + 1) & 1, (kt + 1) * KC);
            cp_commit();
            cp_wait<1>();
        } else {
            cp_wait<0>();
        }
        __syncthreads();

        float* As = sm + (kt & 1) * 8192;
        float* Bs = As + 4352;
#pragma unroll
        for (int ks = 0; ks < 4; ks++) {
            int kb = ks * 8;
            uint32_t a[2][4];
#pragma unroll
            for (int mf = 0; mf < 2; mf++) {
                int mi = m0 + mf * 16 + g;
                a[mf][0] = __float_as_uint(As[(kb + t) * 136 + mi]);
                a[mf][1] = __float_as_uint(As[(kb + t) * 136 + mi + 8]);
                a[mf][2] = __float_as_uint(As[(kb + t + 4) * 136 + mi]);
                a[mf][3] = __float_as_uint(As[(kb + t + 4) * 136 + mi + 8]);
            }
#pragma unroll
            for (int nf = 0; nf < 7; nf++) {
                int ni = n0w + nf * 8 + g;
                uint32_t b0 = __float_as_uint(Bs[(kb + t) * 120 + ni]);
                uint32_t b1 = __float_as_uint(Bs[(kb + t + 4) * 120 + ni]);
                mma8(acc[0][nf], a[0], b0, b1);
                mma8(acc[1][nf], a[1], b0, b1);
            }
        }
        __syncthreads();
    }

    float* Cb = C + (size_t)b * DD * PS;
#pragma unroll
    for (int mf = 0; mf < 2; mf++)
#pragma unroll
        for (int nf = 0; nf < 7; nf++) {
            int row = d0 + m0 + mf * 16 + g;
            int col = n0 + n0w + nf * 8 + t * 2;
            Cb[(size_t)row * PS + col]       = acc[mf][nf][0];
            Cb[(size_t)row * PS + col + 1]   = acc[mf][nf][1];
            Cb[(size_t)(row + 8) * PS + col]     = acc[mf][nf][2];
            Cb[(size_t)(row + 8) * PS + col + 1] = acc[mf][nf][3];
        }
}

// single GEMM: grid (BB, 4 dout-tiles, 2 n-halves)
__global__ __launch_bounds__(256) void gemm_tf32(const float* __restrict__ A,
                                                 const float* __restrict__ B,
                                                 float* __restrict__ C, int K) {
    gemm_body(A, B, C, K, blockIdx.x, blockIdx.y * 128, blockIdx.z * 112);
}

// merged q/k/v GEMM: grid (BB, 8, 3); y = dout-tile(4) x n-half(2), z = which conv
__global__ __launch_bounds__(256) void gemm_tf32_qkv() {
    int z = blockIdx.z;              // 0=q, 1=k, 2=v
    const float* A = g_wtT + (size_t)z * KQ * DD;
    float* C = (z == 0) ? g_q : (z == 1) ? g_k : g_v;
    int d0 = (blockIdx.y & 3) * 128;
    int n0 = (blockIdx.y >> 2) * 112;
    gemm_body(A, g_col, C, KQ, blockIdx.x, d0, n0);
}

// ---------------- fused attention per pixel (stride PS) --------------------
__global__ __launch_bounds__(256) void attention_k() {
    __shared__ float att[64][65];
    __shared__ float buf[4224];

    int p   = blockIdx.x;
    int tid = threadIdx.x;
    int ti  = tid >> 4, tj = tid & 15;
    int i0  = ti * 4,  j0 = tj * 4;

    float acc[4][4];
#pragma unroll
    for (int a = 0; a < 4; a++)
#pragma unroll
        for (int bb = 0; bb < 4; bb++) acc[a][bb] = 0.f;

    for (int c0 = 0; c0 < DD; c0 += 32) {
        for (int idx = tid; idx < 2048; idx += 256) {
            int i = idx >> 5, cc = idx & 31;
            buf[i * 33 + cc]        = g_q[(size_t)(i * DD + c0 + cc) * PS + p];
            buf[2112 + i * 33 + cc] = g_k[(size_t)(i * DD + c0 + cc) * PS + p];
        }
        __syncthreads();
#pragma unroll 4
        for (int cc = 0; cc < 32; cc++) {
            float qv[4], kv[4];
#pragma unroll
            for (int a = 0; a < 4; a++) qv[a] = buf[(i0 + a) * 33 + cc];
#pragma unroll
            for (int bb = 0; bb < 4; bb++) kv[bb] = buf[2112 + (j0 + bb) * 33 + cc];
#pragma unroll
            for (int a = 0; a < 4; a++)
#pragma unroll
                for (int bb = 0; bb < 4; bb++) acc[a][bb] += qv[a] * kv[bb];
        }
        __syncthreads();
    }
    const float rnorm = 0.0441941738241592f;  // 1/sqrt(512)
#pragma unroll
    for (int a = 0; a < 4; a++)
#pragma unroll
        for (int bb = 0; bb < 4; bb++) att[i0 + a][j0 + bb] = acc[a][bb] * rnorm;
    __syncthreads();

    if (tid < 64) {
        float m = -1e30f;
        for (int j = 0; j < 64; j++) m = fmaxf(m, att[tid][j]);
        float s = 0.f;
        for (int j = 0; j < 64; j++) { float e = expf(att[tid][j] - m); att[tid][j] = e; s += e; }
        float inv = 1.f / s;
        for (int j = 0; j < 64; j++) att[tid][j] *= inv;
    }
    __syncthreads();

    for (int c0 = 0; c0 < DD; c0 += 64) {
        for (int idx = tid; idx < 4096; idx += 256) {
            int j = idx >> 6, cc = idx & 63;
            buf[j * 65 + cc] = g_v[(size_t)(j * DD + c0 + cc) * PS + p];
        }
        __syncthreads();
        float a2[4][4];
#pragma unroll
        for (int a = 0; a < 4; a++)
#pragma unroll
            for (int bb = 0; bb < 4; bb++) a2[a][bb] = 0.f;
#pragma unroll 4
        for (int j = 0; j < 64; j++) {
            float av[4], vv[4];
#pragma unroll
            for (int a = 0; a < 4; a++) av[a] = att[i0 + a][j];
#pragma unroll
            for (int bb = 0; bb < 4; bb++) vv[bb] = buf[j * 65 + j0 + bb];
#pragma unroll
            for (int a = 0; a < 4; a++)
#pragma unroll
                for (int bb = 0; bb < 4; bb++) a2[a][bb] += av[a] * vv[bb];
        }
#pragma unroll
        for (int a = 0; a < 4; a++)
#pragma unroll
            for (int bb = 0; bb < 4; bb++)
                g_virt[(size_t)((i0 + a) * DD + c0 + j0 + bb) * PS + p] = a2[a][bb];
        __syncthreads();
    }
}

// ---------------- GroupNorm(1 group) + affine + ReLU, in place -------------
__global__ __launch_bounds__(256) void groupnorm_k(const float* __restrict__ gamma,
                                                   const float* __restrict__ beta) {
    int b = blockIdx.x, tid = threadIdx.x;
    float* v = g_virt + (size_t)b * DD * PS;
    float s1 = 0.f, s2 = 0.f;
    for (int i = tid; i < DD * HW; i += 256) {
        int c = i / HW, p = i % HW;
        float x = v[c * PS + p];
        s1 += x; s2 += x * x;
    }
    __shared__ float sh1[256], sh2[256];
    sh1[tid] = s1; sh2[tid] = s2; __syncthreads();
    for (int s = 128; s > 0; s >>= 1) {
        if (tid < s) { sh1[tid] += sh1[tid + s]; sh2[tid] += sh2[tid + s]; }
        __syncthreads();
    }
    const float invn = 1.f / (DD * HW);
    float mean = sh1[0] * invn;
    float var  = sh2[0] * invn - mean * mean;
    float rstd = rsqrtf(var + 1e-5f);
    for (int i = tid; i < DD * HW; i += 256) {
        int c = i / HW, p = i % HW;
        float x = (v[c * PS + p] - mean) * rstd * gamma[c] + beta[c];
        v[c * PS + p] = fmaxf(x, 0.f);
    }
}

// ---------------- residual + global avg pool + linear head -----------------
__global__ __launch_bounds__(256) void final_k(const float* __restrict__ wp,
                                               float* __restrict__ out) {
    int b = blockIdx.x, tid = threadIdx.x;
    const float* x1 = g_x1 + (size_t)b * DD * PS;
    const float* vc = g_vc + (size_t)b * DD * PS;
    float acc = 0.f;
    for (int d = tid; d < DD; d += 256) {
        float s = 0.f;
        for (int p = 0; p < HW; p++) s += x1[d * PS + p] + vc[d * PS + p];
        acc += s * wp[d];
    }
    __shared__ float sh[256];
    sh[tid] = acc; __syncthreads();
    for (int s = 128; s > 0; s >>= 1) {
        if (tid < s) sh[tid] += sh[tid + s];
        __syncthreads();
    }
    if (tid == 0) out[b] = sh[0] * (1.f / HW);
}

// ---------------------------------------------------------------------------
extern "C" void kernel_launch(void* const* d_in, const int* in_sizes, int n_in,
                              void* d_out, int out_size) {
    const float* x        = (const float*)d_in[0];
    const float* w_reduce = (const float*)d_in[1];
    const float* w_q      = (const float*)d_in[2];
    const float* w_k      = (const float*)d_in[3];
    const float* w_v      = (const float*)d_in[4];
    const float* w_conv   = (const float*)d_in[5];
    const float* gamma    = (const float*)d_in[6];
    const float* beta     = (const float*)d_in[7];
    const float* w_pred   = (const float*)d_in[8];
    float* out = (float*)d_out;

    float *p_xpad, *p_col, *p_x1, *p_virt, *p_vc, *p_wtT, *p_wrT;
    cudaGetSymbolAddress((void**)&p_xpad, g_xpad);
    cudaGetSymbolAddress((void**)&p_col,  g_col);
    cudaGetSymbolAddress((void**)&p_x1,   g_x1);
    cudaGetSymbolAddress((void**)&p_virt, g_virt);
    cudaGetSymbolAddress((void**)&p_vc,   g_vc);
    cudaGetSymbolAddress((void**)&p_wtT,  g_wtT);
    cudaGetSymbolAddress((void**)&p_wrT,  g_wrT);

    cudaFuncSetAttribute(gemm_tf32, cudaFuncAttributeMaxDynamicSharedMemorySize, 65536);
    cudaFuncSetAttribute(gemm_tf32_qkv, cudaFuncAttributeMaxDynamicSharedMemorySize, 65536);

    // weight prep (transpose + tf32 round)
    prep_w<<<(KQ * DD + 255) / 256, 256>>>(w_q, w_k, w_v, w_conv, w_reduce);

    // pad input
    pad_x<<<(BB * CIN * PS) / 1024, 256>>>(x);

    // 1x1 reduce: [512 x 2304] x [2304 x 224] per batch
    gemm_tf32<<<dim3(BB, 4, 2), 256, 65536>>>(p_wrT, p_xpad, p_x1, CIN);

    // im2col of x1, then merged q/k/v convs
    im2col_k<<<(BB * KQ * PS) / 1024, 256>>>(p_x1);
    gemm_tf32_qkv<<<dim3(BB, 8, 3), 256, 65536>>>();

    attention_k<<<HW, 256>>>();
    groupnorm_k<<<BB, 256>>>(gamma, beta);

    // final conv
    im2col_k<<<(BB * KQ * PS) / 1024, 256>>>(p_virt);
    gemm_tf32<<<dim3(BB, 4, 2), 256, 65536>>>(p_wtT + 3 * (size_t)KQ * DD, p_col, p_vc, KQ);

    final_k<<<BB, 256>>>(w_pred, out);
}